// round 10
// baseline (speedup 1.0000x reference)
#include <cuda_runtime.h>

#define BB 16
#define NN 127
#define SS 32
#define EE 16
#define VV 128
#define TT 128   // N+1
#define LL 128
#define XST 132  // xs row stride

// per-(b,t) hidden vectors handed from main -> tail
__device__ float g_hvec[BB * TT * EE];

__global__ __launch_bounds__(256, 8)
void memnet_main(const float* __restrict__ node_fts,
                 const float* __restrict__ edge_fts,
                 const float* __restrict__ graph_fts,
                 const float* __restrict__ adj_mat,
                 const float* __restrict__ query_biases,
                 const float* __restrict__ stories_biases,
                 const float* __restrict__ output_biases,
                 const float* __restrict__ memory_contents)
{
    __shared__ __align__(16) float obtV[VV * 20];   // output_biases, v-major, stride 20
    __shared__ unsigned int sidxw[TT * 8];          // packed u8 story indices [m][8 words]
    __shared__ float2 Qt[VV];                       // (Q0, Q1) per vocab id
    __shared__ float uvec[EE];
    __shared__ float logits[TT];
    __shared__ float probs[TT];
    __shared__ float lgpart[256];
    __shared__ __align__(16) float red0[8 * 16];
    __shared__ __align__(16) float red1[8 * 16];
    __shared__ float redp[8];
    __shared__ int qidx[SS];
    __shared__ unsigned char zrow[TT];
    __shared__ int nzlist[TT];
    __shared__ int warpcnt[4];
    __shared__ int nzcnt;
    __shared__ float wred[4];

    const int tid = threadIdx.x;
    const int bt = blockIdx.x;
    const int b = bt >> 7;
    const int t = bt & 127;

    // ---------------- A: adj flags + ballot (regs), query idx ----------------
    bool nz = false;
    int pos = 0;
    if (tid < TT) {
        if (t < NN && tid < NN) nz = (adj_mat[(b * NN + t) * NN + tid] != 0.f);
        zrow[tid] = nz ? 0 : 1;
        unsigned mask = __ballot_sync(0xFFFFFFFFu, nz);
        if ((tid & 31) == 0) warpcnt[tid >> 5] = __popc(mask);
        pos = __popc(mask & ((1u << (tid & 31)) - 1u));
    } else if (tid < 160) {
        int s = tid - 128;
        float qv = (t < NN) ? node_fts[(b * NN + t) * SS + s]
                            : graph_fts[b * SS + s];
        qidx[s] = min(max((int)qv, 0), VV - 1);
    }
    __syncthreads();

    // ---------------- B: nzlist, u vector, ob table (v-major) ----------------
    if (tid < TT) {
        int w = tid >> 5;
        int off = 0;
        #pragma unroll
        for (int i = 0; i < 4; i++) if (i < w) off += warpcnt[i];
        if (nz) nzlist[off + pos] = tid;
        if (tid == 0) nzcnt = warpcnt[0] + warpcnt[1] + warpcnt[2] + warpcnt[3];
    } else if (tid < 144) {
        // u[e] = sum_s qb[qidx_s, e] * enc(s,e), enc = 1 + (e-7)(s-15)/128
        int e = tid - 128;
        float ae = (float)(e - 7) * (1.f / 128.f);
        float acc = 0.f;
        #pragma unroll
        for (int s = 0; s < SS; s++) {
            int idx = qidx[s];
            float qv = (idx < VV - 1) ? query_biases[idx * EE + e] : 0.f;
            acc += qv * (1.f + ae * (float)(s - 15));
        }
        uvec[e] = acc;
    }
    for (int i = tid; i < VV * EE; i += 256) {
        int v = i >> 4, e = i & 15;
        obtV[v * 20 + e] = (v < VV - 1) ? output_biases[v * EE + e] : 0.f;
    }
    __syncthreads();

    const int K = nzcnt;

    // ---------------- C: stage edge rows (nonzero only) + Q tables + logit init ----------------
    for (int slot = tid; slot < K * 8; slot += 256) {
        int r = slot >> 3, j = slot & 7;
        int m = nzlist[r];
        float4 ef4 = ((const float4*)edge_fts)[((b * NN + t) * NN + m) * 8 + j];
        unsigned int w;
        w  = (unsigned int)min(max((int)ef4.x, 0), 127);
        w |= (unsigned int)min(max((int)ef4.y, 0), 127) << 8;
        w |= (unsigned int)min(max((int)ef4.z, 0), 127) << 16;
        w |= (unsigned int)min(max((int)ef4.w, 0), 127) << 24;
        sidxw[m * 8 + j] = w;
    }
    if (tid < VV) {
        int v = tid;
        float q0 = 0.f, q1 = 0.f;
        if (v < VV - 1) {
            #pragma unroll
            for (int e = 0; e < EE; e++) {
                float sv = stories_biases[v * EE + e];
                float ue = uvec[e];
                q0 += sv * ue;
                q1 += sv * ue * ((float)(e - 7) * (1.f / 128.f));
            }
        }
        Qt[v] = make_float2(q0, q1);
    } else {
        int m = tid - 128;
        float acc = 0.f;
        #pragma unroll
        for (int e = 0; e < EE; e++)
            acc += memory_contents[m * EE + e] * uvec[e];
        logits[m] = acc;
    }
    __syncthreads();

    // ---------------- D: pass-1 scalar gathers -> logit partials ----------------
    {
        int m = tid >> 1, h = tid & 1;
        float acc = 0.f;
        if (zrow[m]) {
            if (h == 0) acc = 32.f * Qt[0].x + 16.f * Qt[0].y;
        } else {
            #pragma unroll
            for (int sw = 0; sw < 4; sw++) {
                unsigned int w = sidxw[m * 8 + h * 4 + sw];
                #pragma unroll
                for (int k = 0; k < 4; k++) {
                    int idx = (w >> (8 * k)) & 255;
                    int s = (h * 4 + sw) * 4 + k;
                    float2 q = Qt[idx];
                    acc += q.x + (float)(s - 15) * q.y;
                }
            }
        }
        lgpart[tid] = acc;
    }
    __syncthreads();

    // ---------------- E: softmax (logits are tiny -> no max shift needed) ----------------
    if (tid < TT) {
        float lv = logits[tid] + lgpart[2 * tid] + lgpart[2 * tid + 1];
        float ev = __expf(lv);
        probs[tid] = ev;
        float sm = ev;
        #pragma unroll
        for (int o = 16; o; o >>= 1) sm += __shfl_xor_sync(0xFFFFFFFFu, sm, o);
        if ((tid & 31) == 0) wred[tid >> 5] = sm;
    }
    __syncthreads();
    if (tid < TT) {
        float inv = 1.f / (wred[0] + wred[1] + wred[2] + wred[3]);
        probs[tid] *= inv;
    }
    __syncthreads();

    // ---------------- F: pass-2 gathers, e-quad vectorized ----------------
    // lane = 4*p + eq : p in 0..7 handles s = it*8+p, eq selects 4 e's (float4).
    {
        int w = tid >> 5, lane = tid & 31;
        int p = lane >> 2, eq = lane & 3;
        float4 a0 = make_float4(0.f, 0.f, 0.f, 0.f);
        float4 a1 = make_float4(0.f, 0.f, 0.f, 0.f);
        float accp = 0.f;
        for (int r = w; r < K; r += 8) {
            int m = nzlist[r];
            float pm = probs[m];
            if (lane == 0) accp += pm;
            #pragma unroll
            for (int it = 0; it < 4; it++) {
                int s = it * 8 + p;
                unsigned int wd = sidxw[m * 8 + (s >> 2)];
                int idx = (wd >> (8 * (s & 3))) & 255;
                const float4 val = *(const float4*)&obtV[idx * 20 + eq * 4];
                float c1 = pm * (float)(s - 15);
                a0.x = fmaf(val.x, pm, a0.x);
                a0.y = fmaf(val.y, pm, a0.y);
                a0.z = fmaf(val.z, pm, a0.z);
                a0.w = fmaf(val.w, pm, a0.w);
                a1.x = fmaf(val.x, c1, a1.x);
                a1.y = fmaf(val.y, c1, a1.y);
                a1.z = fmaf(val.z, c1, a1.z);
                a1.w = fmaf(val.w, c1, a1.w);
            }
        }
        // reduce across the 8 p-lanes sharing each eq (xor 16, 8, 4)
        #pragma unroll
        for (int o = 16; o >= 4; o >>= 1) {
            a0.x += __shfl_xor_sync(0xFFFFFFFFu, a0.x, o);
            a0.y += __shfl_xor_sync(0xFFFFFFFFu, a0.y, o);
            a0.z += __shfl_xor_sync(0xFFFFFFFFu, a0.z, o);
            a0.w += __shfl_xor_sync(0xFFFFFFFFu, a0.w, o);
            a1.x += __shfl_xor_sync(0xFFFFFFFFu, a1.x, o);
            a1.y += __shfl_xor_sync(0xFFFFFFFFu, a1.y, o);
            a1.z += __shfl_xor_sync(0xFFFFFFFFu, a1.z, o);
            a1.w += __shfl_xor_sync(0xFFFFFFFFu, a1.w, o);
        }
        if (lane < 4) {
            *(float4*)&red0[w * 16 + eq * 4] = a0;
            *(float4*)&red1[w * 16 + eq * 4] = a1;
        }
        if (lane == 0) redp[w] = accp;
    }
    __syncthreads();

    // ---------------- G: combine -> hvec, write to global ----------------
    if (tid < EE) {
        int e = tid;
        float O0 = 0.f, O1 = 0.f, sp = 0.f;
        #pragma unroll
        for (int w = 0; w < 8; w++) {
            O0 += red0[w * 16 + e];
            O1 += red1[w * 16 + e];
            sp += redp[w];
        }
        float Z = 1.f - sp;                  // prob mass on zero rows
        float ob0 = obtV[e];                 // table row for idx 0
        O0 += Z * 32.f * ob0;
        O1 += Z * 16.f * ob0;
        float ae = (float)(e - 7) * (1.f / 128.f);
        g_hvec[bt * EE + e] = uvec[e] + O0 + ae * O1;
    }
}

// Tail v4: x = relu(h @ W_out); ret = x @ W_fin; out = ret[t] + ret[graph].
// 512 CTAs (4 node rows + graph each), thread = (l-half, row, v-quad):
// each thread covers 64 l-values -> 64 LDG.128 of W_fin; ~27 warps/SM hide
// L2 latency; partials combined through 2KB smem.
__global__ __launch_bounds__(256, 7)
void memnet_tail(const float* __restrict__ W_out,
                 const float* __restrict__ W_fin,
                 float* __restrict__ out)
{
    __shared__ float wout[EE * LL];        // 16*128
    __shared__ float hs[5 * EE];           // 4 node rows + graph
    __shared__ float xs[5 * XST];
    __shared__ __align__(16) float part[128 * 4];  // lh=1 partials

    const int tid = threadIdx.x;
    const int cta = blockIdx.x;
    const int b = cta >> 5;
    const int chunk = cta & 31;            // 4-row chunk

    for (int i = tid; i < EE * LL; i += 256) wout[i] = W_out[i];
    if (tid < 5 * EE) {
        int r = tid >> 4, e = tid & 15;
        int t = (r < 4) ? chunk * 4 + r : 127;
        hs[tid] = g_hvec[(b * TT + t) * EE + e];
    }
    __syncthreads();

    // xs[r][l] = relu(sum_e hs[r][e] * wout[e][l]),  5*128 outputs
    for (int i = tid; i < 5 * LL; i += 256) {
        int r = i >> 7, l = i & 127;
        float acc = 0.f;
        #pragma unroll
        for (int e = 0; e < EE; e++) acc += hs[r * EE + e] * wout[e * LL + l];
        xs[r * XST + l] = fmaxf(acc, 0.f);
    }
    __syncthreads();

    // main loop: thread = (lh, rp, vq); graph row fused; halves reduced via smem
    {
        int vq = tid & 31, rp = (tid >> 5) & 3, lh = tid >> 7;
        const float4* wf4 = (const float4*)W_fin;
        float4 a  = make_float4(0.f, 0.f, 0.f, 0.f);
        float4 ag = make_float4(0.f, 0.f, 0.f, 0.f);
        #pragma unroll 8
        for (int i = 0; i < 64; i++) {
            int l = lh * 64 + i;
            float4 wv = wf4[l * 32 + vq];
            float x0 = xs[rp * XST + l];
            float xg = xs[4 * XST + l];
            a.x  = fmaf(wv.x, x0, a.x);
            a.y  = fmaf(wv.y, x0, a.y);
            a.z  = fmaf(wv.z, x0, a.z);
            a.w  = fmaf(wv.w, x0, a.w);
            ag.x = fmaf(wv.x, xg, ag.x);
            ag.y = fmaf(wv.y, xg, ag.y);
            ag.z = fmaf(wv.z, xg, ag.z);
            ag.w = fmaf(wv.w, xg, ag.w);
        }
        a.x += ag.x; a.y += ag.y; a.z += ag.z; a.w += ag.w;
        if (lh == 1) *(float4*)&part[(rp * 32 + vq) * 4] = a;
        __syncthreads();
        if (lh == 0) {
            float4 pb = *(const float4*)&part[(rp * 32 + vq) * 4];
            a.x += pb.x; a.y += pb.y; a.z += pb.z; a.w += pb.w;
            int t = chunk * 4 + rp;
            if (t < NN) *(float4*)&out[(b * NN + t) * VV + vq * 4] = a;
        }
    }
}

extern "C" void kernel_launch(void* const* d_in, const int* in_sizes, int n_in,
                              void* d_out, int out_size)
{
    (void)in_sizes; (void)n_in; (void)out_size;
    const float* node_fts        = (const float*)d_in[0];
    const float* edge_fts        = (const float*)d_in[1];
    const float* graph_fts       = (const float*)d_in[2];
    const float* adj_mat         = (const float*)d_in[3];
    // d_in[4] hidden (unused), d_in[5] enc (computed analytically, exact)
    const float* query_biases    = (const float*)d_in[6];
    const float* stories_biases  = (const float*)d_in[7];
    const float* output_biases   = (const float*)d_in[8];
    const float* memory_contents = (const float*)d_in[9];
    // d_in[10] W_int unused (num_hops == 1)
    const float* W_out           = (const float*)d_in[11];
    const float* W_fin           = (const float*)d_in[12];

    memnet_main<<<BB * TT, 256>>>(node_fts, edge_fts, graph_fts, adj_mat,
                                  query_biases, stories_biases, output_biases,
                                  memory_contents);
    memnet_tail<<<BB * 32, 256>>>(W_out, W_fin, (float*)d_out);
}

// round 11
// speedup vs baseline: 1.0083x; 1.0083x over previous
#include <cuda_runtime.h>

#define BB 16
#define NN 127
#define SS 32
#define EE 16
#define VV 128
#define TT 128   // N+1
#define LL 128

__global__ __launch_bounds__(256, 8)
void memnet_fused(const float* __restrict__ node_fts,
                  const float* __restrict__ edge_fts,
                  const float* __restrict__ graph_fts,
                  const float* __restrict__ adj_mat,
                  const float* __restrict__ query_biases,
                  const float* __restrict__ stories_biases,
                  const float* __restrict__ output_biases,
                  const float* __restrict__ memory_contents,
                  const float* __restrict__ W_out,
                  const float* __restrict__ W_fin,
                  float* __restrict__ out)
{
    __shared__ __align__(16) float obtV[VV * 20];   // output_biases, v-major, stride 20
    __shared__ unsigned int sidxw[TT * 8];          // packed u8 story indices [m][8 words]
    __shared__ float2 Qt[VV];                       // (Q0, Q1) per vocab id
    __shared__ float uvec[EE];                      // own-row query embedding
    __shared__ float uvecg[EE];                     // graph-row query embedding
    __shared__ float logits[TT];
    __shared__ float probs[TT];
    __shared__ float lgpart[256];
    __shared__ __align__(16) float red0[8 * 16];
    __shared__ __align__(16) float red1[8 * 16];
    __shared__ float redp[8];
    __shared__ int qidx[SS];
    __shared__ int qidxg[SS];
    __shared__ unsigned char zrow[TT];
    __shared__ int nzlist[TT];
    __shared__ int warpcnt[4];
    __shared__ int nzcnt;
    __shared__ float wred[4];
    __shared__ float hso[EE];                       // own hvec
    __shared__ float hsg[EE];                       // graph hvec
    __shared__ float xsum[LL + 4];                  // relu(x_own)+relu(x_graph)
    __shared__ __align__(16) float part[8 * 32 * 4];

    const int tid = threadIdx.x;
    const int bt = blockIdx.x;
    const int b = bt / NN;
    const int t = bt - b * NN;                      // 0..126 (node rows only)

    // ---------------- A: adj flags + ballot (regs), query idx (own + graph) ----------------
    bool nz = false;
    int pos = 0;
    if (tid < TT) {
        if (tid < NN) nz = (adj_mat[(b * NN + t) * NN + tid] != 0.f);
        zrow[tid] = nz ? 0 : 1;
        unsigned mask = __ballot_sync(0xFFFFFFFFu, nz);
        if ((tid & 31) == 0) warpcnt[tid >> 5] = __popc(mask);
        pos = __popc(mask & ((1u << (tid & 31)) - 1u));
    } else if (tid < 160) {
        int s = tid - 128;
        float qv = node_fts[(b * NN + t) * SS + s];
        qidx[s] = min(max((int)qv, 0), VV - 1);
    } else if (tid < 192) {
        int s = tid - 160;
        float qv = graph_fts[b * SS + s];
        qidxg[s] = min(max((int)qv, 0), VV - 1);
    }
    __syncthreads();

    // ---------------- B: nzlist, u vectors, ob table (v-major) ----------------
    if (tid < TT) {
        int w = tid >> 5;
        int off = 0;
        #pragma unroll
        for (int i = 0; i < 4; i++) if (i < w) off += warpcnt[i];
        if (nz) nzlist[off + pos] = tid;
        if (tid == 0) nzcnt = warpcnt[0] + warpcnt[1] + warpcnt[2] + warpcnt[3];
    } else if (tid < 160) {
        // u[e] = sum_s qb[idx_s, e] * enc(s,e), enc = 1 + (e-7)(s-15)/128
        int e = (tid - 128) & 15;
        bool graph = tid >= 144;
        const int* qi = graph ? qidxg : qidx;
        float ae = (float)(e - 7) * (1.f / 128.f);
        float acc = 0.f;
        #pragma unroll
        for (int s = 0; s < SS; s++) {
            int idx = qi[s];
            float qv = (idx < VV - 1) ? query_biases[idx * EE + e] : 0.f;
            acc += qv * (1.f + ae * (float)(s - 15));
        }
        if (graph) uvecg[e] = acc; else uvec[e] = acc;
    }
    for (int i = tid; i < VV * EE; i += 256) {
        int v = i >> 4, e = i & 15;
        obtV[v * 20 + e] = (v < VV - 1) ? output_biases[v * EE + e] : 0.f;
    }
    __syncthreads();

    const int K = nzcnt;

    // ---------------- C: stage edge rows (nonzero only) + Q tables + logit init ----------------
    for (int slot = tid; slot < K * 8; slot += 256) {
        int r = slot >> 3, j = slot & 7;
        int m = nzlist[r];
        float4 ef4 = ((const float4*)edge_fts)[((b * NN + t) * NN + m) * 8 + j];
        unsigned int w;
        w  = (unsigned int)min(max((int)ef4.x, 0), 127);
        w |= (unsigned int)min(max((int)ef4.y, 0), 127) << 8;
        w |= (unsigned int)min(max((int)ef4.z, 0), 127) << 16;
        w |= (unsigned int)min(max((int)ef4.w, 0), 127) << 24;
        sidxw[m * 8 + j] = w;
    }
    if (tid < VV) {
        int v = tid;
        float q0 = 0.f, q1 = 0.f;
        if (v < VV - 1) {
            #pragma unroll
            for (int e = 0; e < EE; e++) {
                float sv = stories_biases[v * EE + e];
                float ue = uvec[e];
                q0 += sv * ue;
                q1 += sv * ue * ((float)(e - 7) * (1.f / 128.f));
            }
        }
        Qt[v] = make_float2(q0, q1);
    } else {
        int m = tid - 128;
        float acc = 0.f;
        #pragma unroll
        for (int e = 0; e < EE; e++)
            acc += memory_contents[m * EE + e] * uvec[e];
        logits[m] = acc;
    }
    __syncthreads();

    // ---------------- D: pass-1 scalar gathers -> logit partials ----------------
    {
        int m = tid >> 1, h = tid & 1;
        float acc = 0.f;
        if (zrow[m]) {
            if (h == 0) acc = 32.f * Qt[0].x + 16.f * Qt[0].y;
        } else {
            #pragma unroll
            for (int sw = 0; sw < 4; sw++) {
                unsigned int w = sidxw[m * 8 + h * 4 + sw];
                #pragma unroll
                for (int k = 0; k < 4; k++) {
                    int idx = (w >> (8 * k)) & 255;
                    int s = (h * 4 + sw) * 4 + k;
                    float2 q = Qt[idx];
                    acc += q.x + (float)(s - 15) * q.y;
                }
            }
        }
        lgpart[tid] = acc;
    }
    __syncthreads();

    // ---------------- E: softmax (logits are tiny -> no max shift needed) ----------------
    if (tid < TT) {
        float lv = logits[tid] + lgpart[2 * tid] + lgpart[2 * tid + 1];
        float ev = __expf(lv);
        probs[tid] = ev;
        float sm = ev;
        #pragma unroll
        for (int o = 16; o; o >>= 1) sm += __shfl_xor_sync(0xFFFFFFFFu, sm, o);
        if ((tid & 31) == 0) wred[tid >> 5] = sm;
    }
    __syncthreads();
    if (tid < TT) {
        float inv = 1.f / (wred[0] + wred[1] + wred[2] + wred[3]);
        probs[tid] *= inv;
    }
    __syncthreads();

    // ---------------- F: pass-2 gathers, e-quad vectorized ----------------
    {
        int w = tid >> 5, lane = tid & 31;
        int p = lane >> 2, eq = lane & 3;
        float4 a0 = make_float4(0.f, 0.f, 0.f, 0.f);
        float4 a1 = make_float4(0.f, 0.f, 0.f, 0.f);
        float accp = 0.f;
        for (int r = w; r < K; r += 8) {
            int m = nzlist[r];
            float pm = probs[m];
            if (lane == 0) accp += pm;
            #pragma unroll
            for (int it = 0; it < 4; it++) {
                int s = it * 8 + p;
                unsigned int wd = sidxw[m * 8 + (s >> 2)];
                int idx = (wd >> (8 * (s & 3))) & 255;
                const float4 val = *(const float4*)&obtV[idx * 20 + eq * 4];
                float c1 = pm * (float)(s - 15);
                a0.x = fmaf(val.x, pm, a0.x);
                a0.y = fmaf(val.y, pm, a0.y);
                a0.z = fmaf(val.z, pm, a0.z);
                a0.w = fmaf(val.w, pm, a0.w);
                a1.x = fmaf(val.x, c1, a1.x);
                a1.y = fmaf(val.y, c1, a1.y);
                a1.z = fmaf(val.z, c1, a1.z);
                a1.w = fmaf(val.w, c1, a1.w);
            }
        }
        #pragma unroll
        for (int o = 16; o >= 4; o >>= 1) {
            a0.x += __shfl_xor_sync(0xFFFFFFFFu, a0.x, o);
            a0.y += __shfl_xor_sync(0xFFFFFFFFu, a0.y, o);
            a0.z += __shfl_xor_sync(0xFFFFFFFFu, a0.z, o);
            a0.w += __shfl_xor_sync(0xFFFFFFFFu, a0.w, o);
            a1.x += __shfl_xor_sync(0xFFFFFFFFu, a1.x, o);
            a1.y += __shfl_xor_sync(0xFFFFFFFFu, a1.y, o);
            a1.z += __shfl_xor_sync(0xFFFFFFFFu, a1.z, o);
            a1.w += __shfl_xor_sync(0xFFFFFFFFu, a1.w, o);
        }
        if (lane < 4) {
            *(float4*)&red0[w * 16 + eq * 4] = a0;
            *(float4*)&red1[w * 16 + eq * 4] = a1;
        }
        if (lane == 0) redp[w] = accp;
    }
    __syncthreads();

    // ---------------- G: combine -> own hvec + closed-form graph hvec ----------------
    if (tid < EE) {
        int e = tid;
        float O0 = 0.f, O1 = 0.f, sp = 0.f;
        #pragma unroll
        for (int w = 0; w < 8; w++) {
            O0 += red0[w * 16 + e];
            O1 += red1[w * 16 + e];
            sp += redp[w];
        }
        float Z = 1.f - sp;                  // prob mass on zero rows
        float ob0 = obtV[e];                 // table row for idx 0
        O0 += Z * 32.f * ob0;
        O1 += Z * 16.f * ob0;
        float ae = (float)(e - 7) * (1.f / 128.f);
        hso[e] = uvec[e] + O0 + ae * O1;
    } else if (tid < 2 * EE) {
        // graph row: stories all-zero -> Cj constant across m -> o independent of probs
        int e = tid - EE;
        float ae = (float)(e - 7) * (1.f / 128.f);
        float ob0 = obtV[e];
        hsg[e] = uvecg[e] + (32.f + 16.f * ae) * ob0;
    }
    __syncthreads();

    // ---------------- H: xsum[l] = relu(h_own@W_out)[l] + relu(h_g@W_out)[l] ----------------
    if (tid < LL) {
        int l = tid;
        float accO = 0.f, accG = 0.f;
        #pragma unroll
        for (int e = 0; e < EE; e++) {
            float w = W_out[e * LL + l];
            accO = fmaf(hso[e], w, accO);
            accG = fmaf(hsg[e], w, accG);
        }
        xsum[l] = fmaxf(accO, 0.f) + fmaxf(accG, 0.f);
    }
    __syncthreads();

    // ---------------- I: out = xsum @ W_fin (thread = (vq, lh), 16 LDG.128 each) ----------------
    {
        int vq = tid & 31, lh = tid >> 5;      // lh 0..7
        const float4* wf4 = (const float4*)W_fin;
        float4 a = make_float4(0.f, 0.f, 0.f, 0.f);
        #pragma unroll
        for (int i = 0; i < 16; i++) {
            int l = lh * 16 + i;
            float4 wv = wf4[l * 32 + vq];
            float x = xsum[l];
            a.x = fmaf(wv.x, x, a.x);
            a.y = fmaf(wv.y, x, a.y);
            a.z = fmaf(wv.z, x, a.z);
            a.w = fmaf(wv.w, x, a.w);
        }
        if (lh > 0) *(float4*)&part[(lh * 32 + vq) * 4] = a;
        __syncthreads();
        if (lh == 0) {
            #pragma unroll
            for (int j = 1; j < 8; j++) {
                float4 pb = *(const float4*)&part[(j * 32 + vq) * 4];
                a.x += pb.x; a.y += pb.y; a.z += pb.z; a.w += pb.w;
            }
            *(float4*)&out[(b * NN + t) * VV + vq * 4] = a;
        }
    }
}

extern "C" void kernel_launch(void* const* d_in, const int* in_sizes, int n_in,
                              void* d_out, int out_size)
{
    (void)in_sizes; (void)n_in; (void)out_size;
    const float* node_fts        = (const float*)d_in[0];
    const float* edge_fts        = (const float*)d_in[1];
    const float* graph_fts       = (const float*)d_in[2];
    const float* adj_mat         = (const float*)d_in[3];
    // d_in[4] hidden (unused), d_in[5] enc (computed analytically, exact)
    const float* query_biases    = (const float*)d_in[6];
    const float* stories_biases  = (const float*)d_in[7];
    const float* output_biases   = (const float*)d_in[8];
    const float* memory_contents = (const float*)d_in[9];
    // d_in[10] W_int unused (num_hops == 1)
    const float* W_out           = (const float*)d_in[11];
    const float* W_fin           = (const float*)d_in[12];

    memnet_fused<<<BB * NN, 256>>>(node_fts, edge_fts, graph_fts, adj_mat,
                                   query_biases, stories_biases, output_biases,
                                   memory_contents, W_out, W_fin, (float*)d_out);
}

// round 12
// speedup vs baseline: 1.1159x; 1.1068x over previous
#include <cuda_runtime.h>
#include <cuda_fp16.h>

#define BB 16
#define NN 127
#define SS 32
#define EE 16
#define VV 128
#define TT 128   // N+1
#define LL 128

__global__ __launch_bounds__(256, 8)
void memnet_fused(const float* __restrict__ node_fts,
                  const float* __restrict__ edge_fts,
                  const float* __restrict__ graph_fts,
                  const float* __restrict__ adj_mat,
                  const float* __restrict__ query_biases,
                  const float* __restrict__ stories_biases,
                  const float* __restrict__ output_biases,
                  const float* __restrict__ memory_contents,
                  const float* __restrict__ W_out,
                  const float* __restrict__ W_fin,
                  float* __restrict__ out)
{
    __shared__ __align__(16) __half obtH[VV * 20];  // output_biases fp16, v-major, stride 20
    __shared__ unsigned int sidxw[TT * 8];          // packed u8 story indices [m][8 words]
    __shared__ float2 Qt[VV];                       // (Q0, Q1) per vocab id (fp32: softmax path)
    __shared__ float uvec[EE];                      // own-row query embedding
    __shared__ float uvecg[EE];                     // graph-row query embedding
    __shared__ float logits[TT];
    __shared__ float probs[TT];
    __shared__ float lgpart[256];
    __shared__ __align__(16) float red0[8 * 16];
    __shared__ __align__(16) float red1[8 * 16];
    __shared__ float redp[8];
    __shared__ int qidx[SS];
    __shared__ int qidxg[SS];
    __shared__ unsigned char zrow[TT];
    __shared__ int nzlist[TT];
    __shared__ int warpcnt[4];
    __shared__ int nzcnt;
    __shared__ float wred[4];
    __shared__ float hso[EE];                       // own hvec
    __shared__ float hsg[EE];                       // graph hvec
    __shared__ float xsum[LL + 4];                  // relu(x_own)+relu(x_graph)
    __shared__ __align__(16) float part[8 * 32 * 4];

    const int tid = threadIdx.x;
    const int bt = blockIdx.x;
    const int b = bt / NN;
    const int t = bt - b * NN;                      // 0..126 (node rows only)

    // ---------------- A: adj flags + ballot (regs), query idx (own + graph) ----------------
    bool nz = false;
    int pos = 0;
    if (tid < TT) {
        if (tid < NN) nz = (adj_mat[(b * NN + t) * NN + tid] != 0.f);
        zrow[tid] = nz ? 0 : 1;
        unsigned mask = __ballot_sync(0xFFFFFFFFu, nz);
        if ((tid & 31) == 0) warpcnt[tid >> 5] = __popc(mask);
        pos = __popc(mask & ((1u << (tid & 31)) - 1u));
    } else if (tid < 160) {
        int s = tid - 128;
        float qv = node_fts[(b * NN + t) * SS + s];
        qidx[s] = min(max((int)qv, 0), VV - 1);
    } else if (tid < 192) {
        int s = tid - 160;
        float qv = graph_fts[b * SS + s];
        qidxg[s] = min(max((int)qv, 0), VV - 1);
    }
    __syncthreads();

    // ---------------- B: nzlist, u vectors, ob table (fp16, v-major) ----------------
    if (tid < TT) {
        int w = tid >> 5;
        int off = 0;
        #pragma unroll
        for (int i = 0; i < 4; i++) if (i < w) off += warpcnt[i];
        if (nz) nzlist[off + pos] = tid;
        if (tid == 0) nzcnt = warpcnt[0] + warpcnt[1] + warpcnt[2] + warpcnt[3];
    } else if (tid < 160) {
        // u[e] = sum_s qb[idx_s, e] * enc(s,e), enc = 1 + (e-7)(s-15)/128
        int e = (tid - 128) & 15;
        bool graph = tid >= 144;
        const int* qi = graph ? qidxg : qidx;
        float ae = (float)(e - 7) * (1.f / 128.f);
        float acc = 0.f;
        #pragma unroll
        for (int s = 0; s < SS; s++) {
            int idx = qi[s];
            float qv = (idx < VV - 1) ? query_biases[idx * EE + e] : 0.f;
            acc += qv * (1.f + ae * (float)(s - 15));
        }
        if (graph) uvecg[e] = acc; else uvec[e] = acc;
    }
    for (int i = tid; i < VV * EE; i += 256) {
        int v = i >> 4, e = i & 15;
        obtH[v * 20 + e] = __float2half((v < VV - 1) ? output_biases[v * EE + e] : 0.f);
    }
    __syncthreads();

    const int K = nzcnt;

    // ---------------- C: stage edge rows (nonzero only) + Q tables + logit init ----------------
    for (int slot = tid; slot < K * 8; slot += 256) {
        int r = slot >> 3, j = slot & 7;
        int m = nzlist[r];
        float4 ef4 = ((const float4*)edge_fts)[((b * NN + t) * NN + m) * 8 + j];
        unsigned int w;
        w  = (unsigned int)min(max((int)ef4.x, 0), 127);
        w |= (unsigned int)min(max((int)ef4.y, 0), 127) << 8;
        w |= (unsigned int)min(max((int)ef4.z, 0), 127) << 16;
        w |= (unsigned int)min(max((int)ef4.w, 0), 127) << 24;
        sidxw[m * 8 + j] = w;
    }
    if (tid < VV) {
        int v = tid;
        float q0 = 0.f, q1 = 0.f;
        if (v < VV - 1) {
            #pragma unroll
            for (int e = 0; e < EE; e++) {
                float sv = stories_biases[v * EE + e];
                float ue = uvec[e];
                q0 += sv * ue;
                q1 += sv * ue * ((float)(e - 7) * (1.f / 128.f));
            }
        }
        Qt[v] = make_float2(q0, q1);
    } else {
        int m = tid - 128;
        float acc = 0.f;
        #pragma unroll
        for (int e = 0; e < EE; e++)
            acc += memory_contents[m * EE + e] * uvec[e];
        logits[m] = acc;
    }
    __syncthreads();

    // ---------------- D: pass-1 scalar gathers -> logit partials (fp32) ----------------
    {
        int m = tid >> 1, h = tid & 1;
        float acc = 0.f;
        if (zrow[m]) {
            if (h == 0) acc = 32.f * Qt[0].x + 16.f * Qt[0].y;
        } else {
            #pragma unroll
            for (int sw = 0; sw < 4; sw++) {
                unsigned int w = sidxw[m * 8 + h * 4 + sw];
                #pragma unroll
                for (int k = 0; k < 4; k++) {
                    int idx = (w >> (8 * k)) & 255;
                    int s = (h * 4 + sw) * 4 + k;
                    float2 q = Qt[idx];
                    acc += q.x + (float)(s - 15) * q.y;
                }
            }
        }
        lgpart[tid] = acc;
    }
    __syncthreads();

    // ---------------- E: softmax (logits are tiny -> no max shift needed) ----------------
    if (tid < TT) {
        float lv = logits[tid] + lgpart[2 * tid] + lgpart[2 * tid + 1];
        float ev = __expf(lv);
        probs[tid] = ev;
        float sm = ev;
        #pragma unroll
        for (int o = 16; o; o >>= 1) sm += __shfl_xor_sync(0xFFFFFFFFu, sm, o);
        if ((tid & 31) == 0) wred[tid >> 5] = sm;
    }
    __syncthreads();
    if (tid < TT) {
        float inv = 1.f / (wred[0] + wred[1] + wred[2] + wred[3]);
        probs[tid] *= inv;
    }
    __syncthreads();

    // ---------------- F: pass-2 gathers, e-quad vectorized, fp16 table ----------------
    // lane = 4*p + eq : p in 0..7 handles s = it*8+p, eq selects 4 e's (8B of halves).
    {
        int w = tid >> 5, lane = tid & 31;
        int p = lane >> 2, eq = lane & 3;
        float4 a0 = make_float4(0.f, 0.f, 0.f, 0.f);
        float4 a1 = make_float4(0.f, 0.f, 0.f, 0.f);
        float accp = 0.f;
        for (int r = w; r < K; r += 8) {
            int m = nzlist[r];
            float pm = probs[m];
            accp += pm;          // equal across lanes; lane 0's copy is used
            #pragma unroll
            for (int it = 0; it < 4; it++) {
                int s = it * 8 + p;
                unsigned int wd = sidxw[m * 8 + (s >> 2)];
                int idx = (wd >> (8 * (s & 3))) & 255;
                uint2 uv = *(const uint2*)&obtH[idx * 20 + eq * 4];
                float2 f0 = __half22float2(*(__half2*)&uv.x);
                float2 f1 = __half22float2(*(__half2*)&uv.y);
                float c1 = pm * (float)(s - 15);
                a0.x = fmaf(f0.x, pm, a0.x);
                a0.y = fmaf(f0.y, pm, a0.y);
                a0.z = fmaf(f1.x, pm, a0.z);
                a0.w = fmaf(f1.y, pm, a0.w);
                a1.x = fmaf(f0.x, c1, a1.x);
                a1.y = fmaf(f0.y, c1, a1.y);
                a1.z = fmaf(f1.x, c1, a1.z);
                a1.w = fmaf(f1.y, c1, a1.w);
            }
        }
        #pragma unroll
        for (int o = 16; o >= 4; o >>= 1) {
            a0.x += __shfl_xor_sync(0xFFFFFFFFu, a0.x, o);
            a0.y += __shfl_xor_sync(0xFFFFFFFFu, a0.y, o);
            a0.z += __shfl_xor_sync(0xFFFFFFFFu, a0.z, o);
            a0.w += __shfl_xor_sync(0xFFFFFFFFu, a0.w, o);
            a1.x += __shfl_xor_sync(0xFFFFFFFFu, a1.x, o);
            a1.y += __shfl_xor_sync(0xFFFFFFFFu, a1.y, o);
            a1.z += __shfl_xor_sync(0xFFFFFFFFu, a1.z, o);
            a1.w += __shfl_xor_sync(0xFFFFFFFFu, a1.w, o);
        }
        if (lane < 4) {
            *(float4*)&red0[w * 16 + eq * 4] = a0;
            *(float4*)&red1[w * 16 + eq * 4] = a1;
        }
        if (lane == 0) redp[w] = accp;
    }
    __syncthreads();

    // ---------------- G: combine -> own hvec + closed-form graph hvec ----------------
    if (tid < EE) {
        int e = tid;
        float O0 = 0.f, O1 = 0.f, sp = 0.f;
        #pragma unroll
        for (int w = 0; w < 8; w++) {
            O0 += red0[w * 16 + e];
            O1 += red1[w * 16 + e];
            sp += redp[w];
        }
        float Z = 1.f - sp;                          // prob mass on zero rows
        float ob0 = __half2float(obtH[e]);           // table row for idx 0
        O0 += Z * 32.f * ob0;
        O1 += Z * 16.f * ob0;
        float ae = (float)(e - 7) * (1.f / 128.f);
        hso[e] = uvec[e] + O0 + ae * O1;
    } else if (tid < 2 * EE) {
        // graph row: stories all-zero -> Cj constant across m -> o independent of probs
        int e = tid - EE;
        float ae = (float)(e - 7) * (1.f / 128.f);
        float ob0 = __half2float(obtH[e]);
        hsg[e] = uvecg[e] + (32.f + 16.f * ae) * ob0;
    }
    __syncthreads();

    // ---------------- H: xsum[l] = relu(h_own@W_out)[l] + relu(h_g@W_out)[l] ----------------
    if (tid < LL) {
        int l = tid;
        float accO = 0.f, accG = 0.f;
        #pragma unroll
        for (int e = 0; e < EE; e++) {
            float w = W_out[e * LL + l];
            accO = fmaf(hso[e], w, accO);
            accG = fmaf(hsg[e], w, accG);
        }
        xsum[l] = fmaxf(accO, 0.f) + fmaxf(accG, 0.f);
    }
    __syncthreads();

    // ---------------- I: out = xsum @ W_fin, chunked 4-wide (spill-free MLP=4) ----------------
    {
        int vq = tid & 31, lh = tid >> 5;      // lh 0..7, 16 l-values each
        const float4* wp = (const float4*)W_fin + (lh * 16) * 32 + vq;
        const float* xp = xsum + lh * 16;
        float4 a = make_float4(0.f, 0.f, 0.f, 0.f);
        #pragma unroll 1
        for (int c = 0; c < 4; c++) {
            float4 w0 = wp[0];
            float4 w1 = wp[32];
            float4 w2 = wp[64];
            float4 w3 = wp[96];
            float x0 = xp[0], x1 = xp[1], x2 = xp[2], x3 = xp[3];
            a.x = fmaf(w0.x, x0, a.x); a.y = fmaf(w0.y, x0, a.y);
            a.z = fmaf(w0.z, x0, a.z); a.w = fmaf(w0.w, x0, a.w);
            a.x = fmaf(w1.x, x1, a.x); a.y = fmaf(w1.y, x1, a.y);
            a.z = fmaf(w1.z, x1, a.z); a.w = fmaf(w1.w, x1, a.w);
            a.x = fmaf(w2.x, x2, a.x); a.y = fmaf(w2.y, x2, a.y);
            a.z = fmaf(w2.z, x2, a.z); a.w = fmaf(w2.w, x2, a.w);
            a.x = fmaf(w3.x, x3, a.x); a.y = fmaf(w3.y, x3, a.y);
            a.z = fmaf(w3.z, x3, a.z); a.w = fmaf(w3.w, x3, a.w);
            wp += 128;
            xp += 4;
        }
        if (lh > 0) *(float4*)&part[(lh * 32 + vq) * 4] = a;
        __syncthreads();
        if (lh == 0) {
            #pragma unroll
            for (int j = 1; j < 8; j++) {
                float4 pb = *(const float4*)&part[(j * 32 + vq) * 4];
                a.x += pb.x; a.y += pb.y; a.z += pb.z; a.w += pb.w;
            }
            *(float4*)&out[(b * NN + t) * VV + vq * 4] = a;
        }
    }
}

extern "C" void kernel_launch(void* const* d_in, const int* in_sizes, int n_in,
                              void* d_out, int out_size)
{
    (void)in_sizes; (void)n_in; (void)out_size;
    const float* node_fts        = (const float*)d_in[0];
    const float* edge_fts        = (const float*)d_in[1];
    const float* graph_fts       = (const float*)d_in[2];
    const float* adj_mat         = (const float*)d_in[3];
    // d_in[4] hidden (unused), d_in[5] enc (computed analytically, exact)
    const float* query_biases    = (const float*)d_in[6];
    const float* stories_biases  = (const float*)d_in[7];
    const float* output_biases   = (const float*)d_in[8];
    const float* memory_contents = (const float*)d_in[9];
    // d_in[10] W_int unused (num_hops == 1)
    const float* W_out           = (const float*)d_in[11];
    const float* W_fin           = (const float*)d_in[12];

    memnet_fused<<<BB * NN, 256>>>(node_fts, edge_fts, graph_fts, adj_mat,
                                   query_biases, stories_biases, output_biases,
                                   memory_contents, W_out, W_fin, (float*)d_out);
}

// round 13
// speedup vs baseline: 1.2590x; 1.1282x over previous
#include <cuda_runtime.h>
#include <cuda_fp16.h>

#define BB 16
#define NN 127
#define SS 32
#define EE 16
#define VV 128
#define TT 128   // N+1 memory slots
#define LL 128

__global__ __launch_bounds__(256, 8)
void memnet_fused2(const float* __restrict__ node_fts,
                   const float* __restrict__ edge_fts,
                   const float* __restrict__ graph_fts,
                   const float* __restrict__ adj_mat,
                   const float* __restrict__ query_biases,
                   const float* __restrict__ stories_biases,
                   const float* __restrict__ output_biases,
                   const float* __restrict__ memory_contents,
                   const float* __restrict__ W_out,
                   const float* __restrict__ W_fin,
                   float* __restrict__ out)
{
    __shared__ __align__(16) unsigned int sidxw[2][TT * 8];  // u8 indices; ALIASED as `part` in I
    __shared__ __align__(16) __half obtH[VV * 20];           // ob fp16, v-major, stride 20
    __shared__ __half2 QtH[2][VV];                           // packed (Q0,Q1) per half
    __shared__ float logits[2][TT];                          // logits -> exp -> probs (in place)
    __shared__ unsigned char nzlist[2][TT];
    __shared__ unsigned char zrow[2][TT];
    __shared__ int warpcnt[2][4];
    __shared__ int nzcnt[2];
    __shared__ int qidx[3][SS];                              // A, B, graph
    __shared__ float uvec[3][EE];
    __shared__ float hs[2][EE];
    __shared__ float hsg[EE];
    __shared__ float xsum[2][LL];
    __shared__ __align__(16) float red0[8 * 16];             // [half*4+wl][e]
    __shared__ __align__(16) float red1[8 * 16];
    __shared__ float redp[8];
    __shared__ float wred[2][4];

    const int tid = threadIdx.x;
    const int cta = blockIdx.x;
    const int b = cta >> 6;
    const int c = cta & 63;
    const int tA = 2 * c;
    const int tBr = 2 * c + 1;
    const bool stB = (tBr < NN);
    const int tB = stB ? tBr : (NN - 1);     // clamp (dup work, store guarded)

    const int half = tid >> 7;               // 0 = row A, 1 = row B
    const int ht = tid & 127;
    const int myT = half ? tB : tA;

    // ---------------- A: adj flags + ballot (regs kept for B) ----------------
    bool nz = false;
    if (ht < NN) nz = (adj_mat[(b * NN + myT) * NN + ht] != 0.f);
    zrow[half][ht] = nz ? 0 : 1;
    unsigned mask = __ballot_sync(0xFFFFFFFFu, nz);
    const int w4 = (tid >> 5) & 3;
    if ((tid & 31) == 0) warpcnt[half][w4] = __popc(mask);
    const int pos = __popc(mask & ((1u << (tid & 31)) - 1u));
    __syncthreads();

    // ---------------- B: nzlist + nzcnt + query idx + ob table ----------------
    {
        int off = 0;
        #pragma unroll
        for (int i = 0; i < 4; i++) if (i < w4) off += warpcnt[half][i];
        if (nz) nzlist[half][off + pos] = (unsigned char)ht;
        if (ht == 0)
            nzcnt[half] = warpcnt[half][0] + warpcnt[half][1] + warpcnt[half][2] + warpcnt[half][3];
    }
    if (tid < 96) {
        int which = tid >> 5, s = tid & 31;
        float qv;
        if (which == 0)      qv = node_fts[(b * NN + tA) * SS + s];
        else if (which == 1) qv = node_fts[(b * NN + tB) * SS + s];
        else                 qv = graph_fts[b * SS + s];
        qidx[which][s] = min(max((int)qv, 0), VV - 1);
    }
    for (int i = tid; i < VV * EE; i += 256) {
        int v = i >> 4, e = i & 15;
        obtH[v * 20 + e] = __float2half((v < VV - 1) ? output_biases[v * EE + e] : 0.f);
    }
    __syncthreads();

    const int K0 = nzcnt[0], K1 = nzcnt[1];

    // ---------------- C: u vectors (48 thr) + edge staging (rest) ----------------
    if (tid < 48) {
        int which = tid >> 4, e = tid & 15;
        float ae = (float)(e - 7) * (1.f / 128.f);
        float acc = 0.f;
        #pragma unroll
        for (int s = 0; s < SS; s++) {
            int idx = qidx[which][s];
            float qv = (idx < VV - 1) ? query_biases[idx * EE + e] : 0.f;
            acc += qv * (1.f + ae * (float)(s - 15));
        }
        uvec[which][e] = acc;
    } else if (tid < 128) {
        for (int slot = tid - 48; slot < K0 * 8; slot += 80) {
            int r = slot >> 3, j = slot & 7;
            int m = nzlist[0][r];
            float4 ef4 = ((const float4*)edge_fts)[((b * NN + tA) * NN + m) * 8 + j];
            unsigned int w;
            w  = (unsigned int)min(max((int)ef4.x, 0), 127);
            w |= (unsigned int)min(max((int)ef4.y, 0), 127) << 8;
            w |= (unsigned int)min(max((int)ef4.z, 0), 127) << 16;
            w |= (unsigned int)min(max((int)ef4.w, 0), 127) << 24;
            sidxw[0][m * 8 + j] = w;
        }
    } else {
        for (int slot = ht; slot < K1 * 8; slot += 128) {
            int r = slot >> 3, j = slot & 7;
            int m = nzlist[1][r];
            float4 ef4 = ((const float4*)edge_fts)[((b * NN + tB) * NN + m) * 8 + j];
            unsigned int w;
            w  = (unsigned int)min(max((int)ef4.x, 0), 127);
            w |= (unsigned int)min(max((int)ef4.y, 0), 127) << 8;
            w |= (unsigned int)min(max((int)ef4.z, 0), 127) << 16;
            w |= (unsigned int)min(max((int)ef4.w, 0), 127) << 24;
            sidxw[1][m * 8 + j] = w;
        }
    }
    __syncthreads();

    // ---------------- C2: Qt tables (fp16-packed) + logit init, thread=(half, ht) ----------------
    {
        int v = ht;
        float q0 = 0.f, q1 = 0.f;
        if (v < VV - 1) {
            #pragma unroll
            for (int e = 0; e < EE; e++) {
                float sv = stories_biases[v * EE + e];
                float ue = uvec[half][e];
                q0 += sv * ue;
                q1 += sv * ue * ((float)(e - 7) * (1.f / 128.f));
            }
        }
        QtH[half][v] = __floats2half2_rn(q0, q1);
        float acc = 0.f;
        #pragma unroll
        for (int e = 0; e < EE; e++)
            acc += memory_contents[ht * EE + e] * uvec[half][e];
        logits[half][ht] = acc;
    }
    __syncthreads();

    // ---------------- D: pass-1 gathers (LDS.32, 1 thread per (half,m)) ----------------
    {
        int m = ht;
        float acc;
        if (zrow[half][m]) {
            float2 q0 = __half22float2(QtH[half][0]);
            acc = 32.f * q0.x + 16.f * q0.y;
        } else {
            acc = 0.f;
            #pragma unroll
            for (int sw = 0; sw < 8; sw++) {
                unsigned int wd = sidxw[half][m * 8 + sw];
                #pragma unroll
                for (int k = 0; k < 4; k++) {
                    int idx = (wd >> (8 * k)) & 255;
                    float2 q = __half22float2(QtH[half][idx]);
                    int s = sw * 4 + k;
                    acc += q.x + (float)(s - 15) * q.y;
                }
            }
        }
        logits[half][m] += acc;
    }
    __syncthreads();

    // ---------------- E: softmax per half (no max shift; logits tiny) ----------------
    {
        float ev = __expf(logits[half][ht]);
        logits[half][ht] = ev;
        float sm = ev;
        #pragma unroll
        for (int o = 16; o; o >>= 1) sm += __shfl_xor_sync(0xFFFFFFFFu, sm, o);
        if ((tid & 31) == 0) wred[half][w4] = sm;
    }
    __syncthreads();
    {
        float inv = 1.f / (wred[half][0] + wred[half][1] + wred[half][2] + wred[half][3]);
        logits[half][ht] *= inv;          // logits[] now holds normalized probs
    }
    __syncthreads();

    // ---------------- F: pass-2 gathers, e-quad fp16, 4 warps per half ----------------
    {
        int w = tid >> 5;
        int fh = w >> 2, wl = w & 3;
        int lane = tid & 31, p = lane >> 2, eq = lane & 3;
        int Kf = fh ? K1 : K0;
        float4 a0 = make_float4(0.f, 0.f, 0.f, 0.f);
        float4 a1 = make_float4(0.f, 0.f, 0.f, 0.f);
        float accp = 0.f;
        for (int r = wl; r < Kf; r += 4) {
            int m = nzlist[fh][r];
            float pm = logits[fh][m];
            accp += pm;                   // lane 0's copy used
            #pragma unroll
            for (int it = 0; it < 4; it++) {
                int s = it * 8 + p;
                unsigned int wd = sidxw[fh][m * 8 + (s >> 2)];
                int idx = (wd >> (8 * (s & 3))) & 255;
                uint2 uv = *(const uint2*)&obtH[idx * 20 + eq * 4];
                float2 f0 = __half22float2(*(__half2*)&uv.x);
                float2 f1 = __half22float2(*(__half2*)&uv.y);
                float c1 = pm * (float)(s - 15);
                a0.x = fmaf(f0.x, pm, a0.x);
                a0.y = fmaf(f0.y, pm, a0.y);
                a0.z = fmaf(f1.x, pm, a0.z);
                a0.w = fmaf(f1.y, pm, a0.w);
                a1.x = fmaf(f0.x, c1, a1.x);
                a1.y = fmaf(f0.y, c1, a1.y);
                a1.z = fmaf(f1.x, c1, a1.z);
                a1.w = fmaf(f1.y, c1, a1.w);
            }
        }
        #pragma unroll
        for (int o = 16; o >= 4; o >>= 1) {
            a0.x += __shfl_xor_sync(0xFFFFFFFFu, a0.x, o);
            a0.y += __shfl_xor_sync(0xFFFFFFFFu, a0.y, o);
            a0.z += __shfl_xor_sync(0xFFFFFFFFu, a0.z, o);
            a0.w += __shfl_xor_sync(0xFFFFFFFFu, a0.w, o);
            a1.x += __shfl_xor_sync(0xFFFFFFFFu, a1.x, o);
            a1.y += __shfl_xor_sync(0xFFFFFFFFu, a1.y, o);
            a1.z += __shfl_xor_sync(0xFFFFFFFFu, a1.z, o);
            a1.w += __shfl_xor_sync(0xFFFFFFFFu, a1.w, o);
        }
        if (lane < 4) {
            *(float4*)&red0[w * 16 + eq * 4] = a0;
            *(float4*)&red1[w * 16 + eq * 4] = a1;
        }
        if (lane == 0) redp[w] = accp;
    }
    __syncthreads();

    // ---------------- G: combine -> hvec per half + closed-form graph hvec ----------------
    if (tid < 32) {
        int gh = tid >> 4, e = tid & 15;
        float O0 = 0.f, O1 = 0.f, sp = 0.f;
        #pragma unroll
        for (int wl = 0; wl < 4; wl++) {
            O0 += red0[(gh * 4 + wl) * 16 + e];
            O1 += red1[(gh * 4 + wl) * 16 + e];
            sp += redp[gh * 4 + wl];
        }
        float Z = 1.f - sp;                       // prob mass on zero rows
        float ob0 = output_biases[e];             // fp32 row v=0
        O0 += Z * 32.f * ob0;
        O1 += Z * 16.f * ob0;
        float ae = (float)(e - 7) * (1.f / 128.f);
        hs[gh][e] = uvec[gh][e] + O0 + ae * O1;
    } else if (tid < 48) {
        // graph row: stories all-zero -> o independent of probs (closed form)
        int e = tid - 32;
        float ae = (float)(e - 7) * (1.f / 128.f);
        hsg[e] = uvec[2][e] + (32.f + 16.f * ae) * output_biases[e];
    }
    __syncthreads();

    // ---------------- H: xsum[half][l] = relu(h_half@W_out) + relu(h_g@W_out) ----------------
    {
        int l = ht;
        float accO = 0.f, accG = 0.f;
        #pragma unroll
        for (int e = 0; e < EE; e++) {
            float w = W_out[e * LL + l];
            accO = fmaf(hs[half][e], w, accO);
            accG = fmaf(hsg[e], w, accG);
        }
        xsum[half][l] = fmaxf(accO, 0.f) + fmaxf(accG, 0.f);
    }
    __syncthreads();

    // ---------------- I: both rows @ W_fin, wv loads shared; partials in dead sidxw ----------------
    {
        int vq = tid & 31, lh = tid >> 5;          // 8 lh groups x 16 l
        const float4* wp = (const float4*)W_fin + (lh * 16) * 32 + vq;
        float4 aA = make_float4(0.f, 0.f, 0.f, 0.f);
        float4 aB = make_float4(0.f, 0.f, 0.f, 0.f);
        int l = lh * 16;
        #pragma unroll 1
        for (int ch = 0; ch < 8; ch++) {
            float4 w0 = wp[0];
            float4 w1 = wp[32];
            float xA0 = xsum[0][l], xA1 = xsum[0][l + 1];
            float xB0 = xsum[1][l], xB1 = xsum[1][l + 1];
            aA.x = fmaf(w0.x, xA0, aA.x); aA.y = fmaf(w0.y, xA0, aA.y);
            aA.z = fmaf(w0.z, xA0, aA.z); aA.w = fmaf(w0.w, xA0, aA.w);
            aB.x = fmaf(w0.x, xB0, aB.x); aB.y = fmaf(w0.y, xB0, aB.y);
            aB.z = fmaf(w0.z, xB0, aB.z); aB.w = fmaf(w0.w, xB0, aB.w);
            aA.x = fmaf(w1.x, xA1, aA.x); aA.y = fmaf(w1.y, xA1, aA.y);
            aA.z = fmaf(w1.z, xA1, aA.z); aA.w = fmaf(w1.w, xA1, aA.w);
            aB.x = fmaf(w1.x, xB1, aB.x); aB.y = fmaf(w1.y, xB1, aB.y);
            aB.z = fmaf(w1.z, xB1, aB.z); aB.w = fmaf(w1.w, xB1, aB.w);
            wp += 64;
            l += 2;
        }
        float4* part = (float4*)&sidxw[0][0];      // sidxw dead after F; 7.2KB used of 8KB
        if (lh > 0) {
            part[((lh - 1) * 2 + 0) * 32 + vq] = aA;
            part[((lh - 1) * 2 + 1) * 32 + vq] = aB;
        }
        __syncthreads();
        if (lh == 0) {
            #pragma unroll
            for (int j = 0; j < 7; j++) {
                float4 pa = part[(j * 2 + 0) * 32 + vq];
                float4 pb = part[(j * 2 + 1) * 32 + vq];
                aA.x += pa.x; aA.y += pa.y; aA.z += pa.z; aA.w += pa.w;
                aB.x += pb.x; aB.y += pb.y; aB.z += pb.z; aB.w += pb.w;
            }
            *(float4*)&out[(b * NN + tA) * VV + vq * 4] = aA;
            if (stB) *(float4*)&out[(b * NN + tBr) * VV + vq * 4] = aB;
        }
    }
}

extern "C" void kernel_launch(void* const* d_in, const int* in_sizes, int n_in,
                              void* d_out, int out_size)
{
    (void)in_sizes; (void)n_in; (void)out_size;
    const float* node_fts        = (const float*)d_in[0];
    const float* edge_fts        = (const float*)d_in[1];
    const float* graph_fts       = (const float*)d_in[2];
    const float* adj_mat         = (const float*)d_in[3];
    // d_in[4] hidden (unused), d_in[5] enc (computed analytically, exact)
    const float* query_biases    = (const float*)d_in[6];
    const float* stories_biases  = (const float*)d_in[7];
    const float* output_biases   = (const float*)d_in[8];
    const float* memory_contents = (const float*)d_in[9];
    // d_in[10] W_int unused (num_hops == 1)
    const float* W_out           = (const float*)d_in[11];
    const float* W_fin           = (const float*)d_in[12];

    memnet_fused2<<<BB * 64, 256>>>(node_fts, edge_fts, graph_fts, adj_mat,
                                    query_biases, stories_biases, output_biases,
                                    memory_contents, W_out, W_fin, (float*)d_out);
}